// round 16
// baseline (speedup 1.0000x reference)
#include <cuda_runtime.h>
#include <cuda_fp16.h>
#include <cstdint>

#define NN 50000
#define NE 800000

// ---------------- static device scratch ----------------
__device__ int    g_cnt[NN];
__device__ int    g_fill[NN];
__device__ int    g_rowptr[NN + 1];
__device__ float  g_invdeg[NN];
__device__ int    g_csr[NE];
__device__ int    g_blksum[64];
__device__ uint4  g_xh[(size_t)NN * 16];   // x fp16 (128 cols)
__device__ uint4  g_hh[(size_t)NN * 32];   // hidden activations fp16
__device__ uint4  g_mh[(size_t)NN * 32];   // aggregated mean fp16
__device__ float4 g_pre[(size_t)NN * 64];  // pre-BN output: fp32 (layer2) or fp16 (layers 0/1)
__device__ __half g_wh[262144];            // all 6 weights fp16, [D][K]
__device__ float  g_sum[768];              // 3 layers x 256
__device__ float  g_sumsq[768];

#define OFF_WN0 0
#define OFF_WS0 32768
#define OFF_WN1 65536
#define OFF_WS1 131072
#define OFF_WN2 196608
#define OFF_WS2 229376

#define AST 20   // unsigned units per smem row (80B): 16B-aligned rows, ldmatrix conflict-free

// ---------------- helpers ----------------
__device__ __forceinline__ void mma_fp16(float* c, const unsigned* a, const unsigned* b) {
    asm("mma.sync.aligned.m16n8k16.row.col.f32.f16.f16.f32 "
        "{%0,%1,%2,%3}, {%4,%5,%6,%7}, {%8,%9}, {%0,%1,%2,%3};"
        : "+f"(c[0]), "+f"(c[1]), "+f"(c[2]), "+f"(c[3])
        : "r"(a[0]), "r"(a[1]), "r"(a[2]), "r"(a[3]),
          "r"(b[0]), "r"(b[1]));
}
__device__ __forceinline__ void ldsm_x4(unsigned* r, uint32_t addr) {
    asm volatile("ldmatrix.sync.aligned.m8n8.x4.shared.b16 {%0,%1,%2,%3}, [%4];"
        : "=r"(r[0]), "=r"(r[1]), "=r"(r[2]), "=r"(r[3]) : "r"(addr));
}
__device__ __forceinline__ void ldsm_x2(unsigned* r, uint32_t addr) {
    asm volatile("ldmatrix.sync.aligned.m8n8.x2.shared.b16 {%0,%1}, [%2];"
        : "=r"(r[0]), "=r"(r[1]) : "r"(addr));
}
__device__ __forceinline__ void cp_async16(uint32_t dst, const void* src, int src_size) {
    asm volatile("cp.async.cg.shared.global [%0], [%1], 16, %2;"
        :: "r"(dst), "l"(src), "r"(src_size));
}
__device__ __forceinline__ void cp_commit() {
    asm volatile("cp.async.commit_group;");
}
__device__ __forceinline__ void cp_wait0() {
    asm volatile("cp.async.wait_group 0;");
}

// ---------------- CSR build ----------------
__global__ void k_zero_cnt() {
    int i = blockIdx.x * blockDim.x + threadIdx.x;
    if (i < NN) { g_cnt[i] = 0; g_fill[i] = 0; }
    if (i < 768) { g_sum[i] = 0.f; g_sumsq[i] = 0.f; }
}

__global__ void k_hist(const int* __restrict__ dst) {
    int e = blockIdx.x * blockDim.x + threadIdx.x;
    if (e < NE) atomicAdd(&g_cnt[dst[e]], 1);
}

__global__ void k_scan1() {
    __shared__ int wsum[32];
    const int tid  = threadIdx.x;
    const int lane = tid & 31;
    const int wid  = tid >> 5;
    const int i = blockIdx.x * 1024 + tid;
    int v = (i < NN) ? g_cnt[i] : 0;
    int x = v;
    #pragma unroll
    for (int d = 1; d < 32; d <<= 1) {
        int t = __shfl_up_sync(0xffffffffu, x, d);
        if (lane >= d) x += t;
    }
    if (lane == 31) wsum[wid] = x;
    __syncthreads();
    if (wid == 0) {
        int w = wsum[lane];
        #pragma unroll
        for (int d = 1; d < 32; d <<= 1) {
            int t = __shfl_up_sync(0xffffffffu, w, d);
            if (lane >= d) w += t;
        }
        wsum[lane] = w;
    }
    __syncthreads();
    int incl = x + (wid ? wsum[wid - 1] : 0);
    if (i < NN) {
        g_rowptr[i + 1] = incl;
        g_invdeg[i] = 1.0f / (float)max(v, 1);
    }
    if (tid == 1023) g_blksum[blockIdx.x] = incl;
}

__global__ void k_scan23() {
    __shared__ int sv[64];
    const int tid = threadIdx.x;
    const int bid = blockIdx.x;
    if (tid < 64) sv[tid] = (tid < bid) ? g_blksum[tid] : 0;
    __syncthreads();
    if (tid < 32) {
        int v = sv[tid] + sv[tid + 32];
        #pragma unroll
        for (int d = 16; d; d >>= 1) v += __shfl_down_sync(0xffffffffu, v, d);
        if (tid == 0) sv[0] = v;
    }
    __syncthreads();
    const int off = sv[0];
    const int i = bid * 1024 + tid;
    if (i < NN) g_rowptr[i + 1] += off;
    if (i == 0) g_rowptr[0] = 0;
}

__global__ void k_fill(const int* __restrict__ src, const int* __restrict__ dst) {
    int e = blockIdx.x * blockDim.x + threadIdx.x;
    if (e < NE) {
        int d = dst[e];
        int p = g_rowptr[d] + atomicAdd(&g_fill[d], 1);
        g_csr[p] = src[e];
    }
}

// ---------------- x -> fp16 convert ----------------
__global__ void k_cvtx(const float* __restrict__ x) {
    const int total = NN * 16;
    int i = blockIdx.x * blockDim.x + threadIdx.x;
    if (i >= total) return;
    const float4* xp = reinterpret_cast<const float4*>(x);
    float4 a = xp[i * 2], b = xp[i * 2 + 1];
    uint4 o;
    __half2* op = (__half2*)&o;
    op[0] = __floats2half2_rn(a.x, a.y);
    op[1] = __floats2half2_rn(a.z, a.w);
    op[2] = __floats2half2_rn(b.x, b.y);
    op[3] = __floats2half2_rn(b.z, b.w);
    g_xh[i] = o;
}

// ---------------- all 6 weight transposes in one launch ----------------
__global__ void k_cvtw_all(const float* __restrict__ w0, const float* __restrict__ w1,
                           const float* __restrict__ w2, const float* __restrict__ w3,
                           const float* __restrict__ w4, const float* __restrict__ w5) {
    __shared__ float t[32][33];
    const int wi = blockIdx.z;
    const float* w; int K, D, off;
    switch (wi) {
        case 0:  w = w0; K = 128; D = 256; off = OFF_WN0; break;
        case 1:  w = w1; K = 128; D = 256; off = OFF_WS0; break;
        case 2:  w = w2; K = 256; D = 256; off = OFF_WN1; break;
        case 3:  w = w3; K = 256; D = 256; off = OFF_WS1; break;
        case 4:  w = w4; K = 256; D = 128; off = OFF_WN2; break;
        default: w = w5; K = 256; D = 128; off = OFF_WS2; break;
    }
    const int d0 = blockIdx.x * 32, k0 = blockIdx.y * 32;
    if (d0 >= D || k0 >= K) return;
    const int tx = threadIdx.x, ty = threadIdx.y;
    #pragma unroll
    for (int i = ty; i < 32; i += 8)
        t[i][tx] = w[(size_t)(k0 + i) * D + d0 + tx];
    __syncthreads();
    #pragma unroll
    for (int i = ty; i < 32; i += 8)
        g_wh[off + (size_t)(d0 + i) * K + k0 + tx] = __float2half_rn(t[tx][i]);
}

// ---------------- mean aggregation (4-edge batched loads, in-order accumulate) ----------------
template<int DIN, bool FROMX>
__global__ void k_agg() {
    const int TPN = DIN / 8;
    int t = blockIdx.x * blockDim.x + threadIdx.x;
    int node = t / TPN;
    if (node >= NN) return;
    int c8 = t % TPN;
    const uint4* __restrict__ hin = FROMX ? g_xh : g_hh;
    int beg = g_rowptr[node], end = g_rowptr[node + 1];
    float a0 = 0.f, a1 = 0.f, a2 = 0.f, a3 = 0.f;
    float a4 = 0.f, a5 = 0.f, a6 = 0.f, a7 = 0.f;

    auto accum = [&](uint4 u) {
        const __half2* hp = (const __half2*)&u;
        float2 f0 = __half22float2(hp[0]);
        float2 f1 = __half22float2(hp[1]);
        float2 f2 = __half22float2(hp[2]);
        float2 f3 = __half22float2(hp[3]);
        a0 += f0.x; a1 += f0.y; a2 += f1.x; a3 += f1.y;
        a4 += f2.x; a5 += f2.y; a6 += f3.x; a7 += f3.y;
    };

    int e = beg;
    for (; e + 4 <= end; e += 4) {
        // batch index loads, then 4 independent row gathers (MLP=4),
        // accumulate in original edge order (bit-identical numerics)
        int s0 = g_csr[e];
        int s1 = g_csr[e + 1];
        int s2 = g_csr[e + 2];
        int s3 = g_csr[e + 3];
        uint4 u0 = hin[(size_t)s0 * TPN + c8];
        uint4 u1 = hin[(size_t)s1 * TPN + c8];
        uint4 u2 = hin[(size_t)s2 * TPN + c8];
        uint4 u3 = hin[(size_t)s3 * TPN + c8];
        accum(u0); accum(u1); accum(u2); accum(u3);
    }
    for (; e < end; e++) {
        int s = g_csr[e];
        accum(hin[(size_t)s * TPN + c8]);
    }

    float inv = g_invdeg[node];
    uint4 o;
    __half2* op = (__half2*)&o;
    op[0] = __floats2half2_rn(a0 * inv, a1 * inv);
    op[1] = __floats2half2_rn(a2 * inv, a3 * inv);
    op[2] = __floats2half2_rn(a4 * inv, a5 * inv);
    op[3] = __floats2half2_rn(a6 * inv, a7 * inv);
    g_mh[(size_t)node * TPN + c8] = o;
}

// ---------------- fused dual GEMM: 128x64 tile, 32-wide K chunks, cp.async x2 ----------------
// HALFPRE: store pre-activations as fp16 (layers 0/1); else fp32 (layer 2).
template<int K, int DOUT, bool FROMX, bool HALFPRE>
__global__ __launch_bounds__(256) void k_gemm(
    int off1, int off2, const float* __restrict__ bias, int layer)
{
    __shared__ unsigned As2[2][128 * AST];
    __shared__ unsigned Bs2[2][64 * AST];

    const int tid    = threadIdx.x;
    const int lane   = tid & 31;
    const int wid    = tid >> 5;
    const int mbase  = (wid >> 1) * 32;
    const int nbase  = (wid & 1) * 32;
    const int n0 = blockIdx.x * 64;
    const int m0 = blockIdx.y * 128;

    const int a_row = tid >> 1;         // 0..127
    const int a_g   = tid & 1;          // stages 16B groups {a_g, a_g+2} of 4
    const int b_n   = tid >> 2;         // 0..63
    const int b_g   = tid & 3;          // one 16B group of 4

    const int THK = K / 8;
    const int CPP = K / 32;             // 32-wide chunks per phase
    const int NCH = 2 * CPP;
    const uint4* A1 = g_mh;
    const uint4* A2 = FROMX ? g_xh : g_hh;
    const __half* B1w = g_wh + off1;
    const __half* B2w = g_wh + off2;

    const uint32_t sbA = (uint32_t)__cvta_generic_to_shared(&As2[0][0]);
    const uint32_t sbB = (uint32_t)__cvta_generic_to_shared(&Bs2[0][0]);
    const uint32_t ABYTES = 128u * AST * 4u;
    const uint32_t BBYTES = 64u * AST * 4u;

    const uint32_t dstA0 = sbA + 4u * (a_row * AST + a_g * 4);
    const uint32_t dstA1 = dstA0 + 32u;        // group a_g+2
    const uint32_t dstB  = sbB + 4u * (b_n * AST + b_g * 4);

    const int gr   = m0 + a_row;
    const int grc  = (gr < NN) ? gr : 0;
    const int asz  = (gr < NN) ? 16 : 0;

    // ldmatrix addresses (buffer 0, k16-half 0)
    const int quad = lane >> 3, lr = lane & 7;
    uint32_t addrA[2], addrB[4];
    #pragma unroll
    for (int sm = 0; sm < 2; sm++) {
        int row = mbase + sm * 16 + (quad & 1) * 8 + lr;
        int kp  = (quad >> 1) * 4;
        addrA[sm] = sbA + 4u * (row * AST + kp);
    }
    {
        const int l16 = lane & 15;
        #pragma unroll
        for (int sn = 0; sn < 4; sn++) {
            int row = nbase + sn * 8 + (l16 & 7);
            int kp  = (l16 >> 3) * 4;
            addrB[sn] = sbB + 4u * (row * AST + kp);
        }
    }

    float acc[2][4][4];
    #pragma unroll
    for (int i = 0; i < 2; i++)
        #pragma unroll
        for (int j = 0; j < 4; j++)
            #pragma unroll
            for (int r = 0; r < 4; r++) acc[i][j][r] = 0.f;

    auto stage = [&](int c, int b) {
        const int phase = (c >= CPP);
        const int k0    = (c - phase * CPP) * 32;
        const uint4*  A = phase ? A2 : A1;
        const __half* B = phase ? B2w : B1w;
        const uint4* as = A + (size_t)grc * THK + (k0 >> 3);
        cp_async16(dstA0 + b * ABYTES, as + a_g,     asz);
        cp_async16(dstA1 + b * ABYTES, as + a_g + 2, asz);
        cp_async16(dstB  + b * BBYTES,
                   B + (size_t)(n0 + b_n) * K + k0 + b_g * 8, 16);
        cp_commit();
    };

    stage(0, 0);
    cp_wait0();
    __syncthreads();

    for (int c = 0; c < NCH; c++) {
        const int buf = c & 1;
        if (c + 1 < NCH) stage(c + 1, buf ^ 1);

        const uint32_t oA = buf * ABYTES;
        const uint32_t oB = buf * BBYTES;
        #pragma unroll
        for (int h = 0; h < 2; h++) {
            const uint32_t hk = h * 32u;   // +8 unsigned = second k16 half
            unsigned af[2][4];
            ldsm_x4(af[0], addrA[0] + oA + hk);
            ldsm_x4(af[1], addrA[1] + oA + hk);
            #pragma unroll
            for (int sn = 0; sn < 4; sn++) {
                unsigned bf[2];
                ldsm_x2(bf, addrB[sn] + oB + hk);
                mma_fp16(acc[0][sn], af[0], bf);
                mma_fp16(acc[1][sn], af[1], bf);
            }
        }

        if (c + 1 < NCH) {
            cp_wait0();
            __syncthreads();
        }
    }

    // ---------------- epilogue: bias + store + BN partials ----------------
    float*  Cf = (float*)g_pre;
    __half* Ch = (__half*)g_pre;

    #pragma unroll
    for (int sn = 0; sn < 4; sn++) {
        const int colg = n0 + nbase + sn * 8 + 2 * (lane & 3);
        const float bb0 = bias[colg];
        const float bb1 = bias[colg + 1];
        float s0 = 0.f, s1 = 0.f, q0 = 0.f, q1 = 0.f;
        #pragma unroll
        for (int sm = 0; sm < 2; sm++) {
            const int r0 = m0 + mbase + sm * 16 + (lane >> 2);
            const int r1 = r0 + 8;
            float v0 = acc[sm][sn][0] + bb0;
            float v1 = acc[sm][sn][1] + bb1;
            float v2 = acc[sm][sn][2] + bb0;
            float v3 = acc[sm][sn][3] + bb1;
            if (r0 < NN) {
                if (HALFPRE)
                    *reinterpret_cast<__half2*>(Ch + (size_t)r0 * DOUT + colg) =
                        __floats2half2_rn(v0, v1);
                else
                    *reinterpret_cast<float2*>(Cf + (size_t)r0 * DOUT + colg) =
                        make_float2(v0, v1);
                s0 += v0; q0 += v0 * v0;
                s1 += v1; q1 += v1 * v1;
            }
            if (r1 < NN) {
                if (HALFPRE)
                    *reinterpret_cast<__half2*>(Ch + (size_t)r1 * DOUT + colg) =
                        __floats2half2_rn(v2, v3);
                else
                    *reinterpret_cast<float2*>(Cf + (size_t)r1 * DOUT + colg) =
                        make_float2(v2, v3);
                s0 += v2; q0 += v2 * v2;
                s1 += v3; q1 += v3 * v3;
            }
        }
        #pragma unroll
        for (int d = 16; d >= 4; d >>= 1) {
            s0 += __shfl_down_sync(0xffffffffu, s0, d);
            s1 += __shfl_down_sync(0xffffffffu, s1, d);
            q0 += __shfl_down_sync(0xffffffffu, q0, d);
            q1 += __shfl_down_sync(0xffffffffu, q1, d);
        }
        if (lane < 4) {
            const int cg = n0 + nbase + sn * 8 + 2 * lane;
            atomicAdd(&g_sum  [layer * 256 + cg],     s0);
            atomicAdd(&g_sum  [layer * 256 + cg + 1], s1);
            atomicAdd(&g_sumsq[layer * 256 + cg],     q0);
            atomicAdd(&g_sumsq[layer * 256 + cg + 1], q1);
        }
    }
}

// ---------------- BN finalize (in-block) + apply ----------------
// HALFIN: pre stored as fp16 (layers 0/1); else fp32 (layer 2).
template<int DOUT, bool RELU, bool TOOUT, bool HALFIN>
__global__ __launch_bounds__(256) void k_bnapply(
    const float* __restrict__ gamma, const float* __restrict__ beta,
    int layer, float* __restrict__ outp)
{
    __shared__ float s_scale[DOUT], s_shift[DOUT];
    const int tid = threadIdx.x;
    if (tid < DOUT) {
        float mu  = g_sum[layer * 256 + tid] * (1.0f / NN);
        float var = g_sumsq[layer * 256 + tid] * (1.0f / NN) - mu * mu;
        float sc  = gamma[tid] * rsqrtf(var + 1e-5f);
        s_scale[tid] = sc;
        s_shift[tid] = beta[tid] - mu * sc;
    }
    __syncthreads();

    const int total = NN * (DOUT / 8);
    int i = blockIdx.x * blockDim.x + tid;
    if (i >= total) return;
    int c8 = (i % (DOUT / 8)) * 8;
    float p[8];
    if (HALFIN) {
        uint4 u = reinterpret_cast<const uint4*>(g_pre)[i];
        const __half2* hp = (const __half2*)&u;
        float2 f0 = __half22float2(hp[0]);
        float2 f1 = __half22float2(hp[1]);
        float2 f2 = __half22float2(hp[2]);
        float2 f3 = __half22float2(hp[3]);
        p[0] = f0.x; p[1] = f0.y; p[2] = f1.x; p[3] = f1.y;
        p[4] = f2.x; p[5] = f2.y; p[6] = f3.x; p[7] = f3.y;
    } else {
        float4 v0 = g_pre[i * 2];
        float4 v1 = g_pre[i * 2 + 1];
        p[0] = v0.x; p[1] = v0.y; p[2] = v0.z; p[3] = v0.w;
        p[4] = v1.x; p[5] = v1.y; p[6] = v1.z; p[7] = v1.w;
    }
    float r[8];
    #pragma unroll
    for (int j = 0; j < 8; j++) {
        r[j] = p[j] * s_scale[c8 + j] + s_shift[c8 + j];
        if (RELU) r[j] = fmaxf(r[j], 0.f);
    }
    if (TOOUT) {
        float4* op = reinterpret_cast<float4*>(outp);
        op[i * 2]     = make_float4(r[0], r[1], r[2], r[3]);
        op[i * 2 + 1] = make_float4(r[4], r[5], r[6], r[7]);
    } else {
        uint4 o;
        __half2* hp = (__half2*)&o;
        hp[0] = __floats2half2_rn(r[0], r[1]);
        hp[1] = __floats2half2_rn(r[2], r[3]);
        hp[2] = __floats2half2_rn(r[4], r[5]);
        hp[3] = __floats2half2_rn(r[6], r[7]);
        g_hh[i] = o;
    }
}

// ---------------- launch ----------------
extern "C" void kernel_launch(void* const* d_in, const int* in_sizes, int n_in,
                              void* d_out, int out_size) {
    const float* x    = (const float*)d_in[0];
    const int*   ei   = (const int*)d_in[1];
    const int*   esrc = ei;
    const int*   edst = ei + NE;
    const float* wn0 = (const float*)d_in[2];
    const float* ws0 = (const float*)d_in[3];
    const float* b0  = (const float*)d_in[4];
    const float* g0  = (const float*)d_in[5];
    const float* be0 = (const float*)d_in[6];
    const float* wn1 = (const float*)d_in[7];
    const float* ws1 = (const float*)d_in[8];
    const float* b1  = (const float*)d_in[9];
    const float* g1  = (const float*)d_in[10];
    const float* be1 = (const float*)d_in[11];
    const float* wn2 = (const float*)d_in[12];
    const float* ws2 = (const float*)d_in[13];
    const float* b2  = (const float*)d_in[14];
    const float* g2  = (const float*)d_in[15];
    const float* be2 = (const float*)d_in[16];
    float* out = (float*)d_out;

    const int NBLK = (NN + 1023) / 1024;   // 49

    k_zero_cnt<<<(NN + 255) / 256, 256>>>();
    k_hist<<<(NE + 255) / 256, 256>>>(edst);
    k_scan1<<<NBLK, 1024>>>();
    k_scan23<<<NBLK, 1024>>>();
    k_fill<<<(NE + 255) / 256, 256>>>(esrc, edst);
    k_cvtx<<<(NN * 16 + 255) / 256, 256>>>(x);
    k_cvtw_all<<<dim3(8, 8, 6), dim3(32, 8)>>>(wn0, ws0, wn1, ws1, wn2, ws2);

    const int M_TILES = (NN + 127) / 128;

    // ---- layer 0: 128 -> 256 (fp16 pre) ----
    k_agg<128, true><<<(NN * 16 + 255) / 256, 256>>>();
    k_gemm<128, 256, true, true><<<dim3(4, M_TILES), 256>>>(OFF_WN0, OFF_WS0, b0, 0);
    k_bnapply<256, true, false, true><<<(NN * 32 + 255) / 256, 256>>>(g0, be0, 0, nullptr);

    // ---- layer 1: 256 -> 256 (fp16 pre) ----
    k_agg<256, false><<<(NN * 32 + 255) / 256, 256>>>();
    k_gemm<256, 256, false, true><<<dim3(4, M_TILES), 256>>>(OFF_WN1, OFF_WS1, b1, 1);
    k_bnapply<256, true, false, true><<<(NN * 32 + 255) / 256, 256>>>(g1, be1, 1, nullptr);

    // ---- layer 2: 256 -> 128 (fp32 pre, fp32 out) ----
    k_agg<256, false><<<(NN * 32 + 255) / 256, 256>>>();
    k_gemm<256, 128, false, false><<<dim3(2, M_TILES), 256>>>(OFF_WN2, OFF_WS2, b2, 2);
    k_bnapply<128, false, true, false><<<(NN * 16 + 255) / 256, 256>>>(g2, be2, 2, out);
}

// round 17
// speedup vs baseline: 1.0293x; 1.0293x over previous
#include <cuda_runtime.h>
#include <cuda_fp16.h>
#include <cstdint>

#define NN 50000
#define NE 800000

// ---------------- static device scratch ----------------
__device__ int    g_cnt[NN];
__device__ int    g_fill[NN];
__device__ int    g_rowptr[NN + 1];
__device__ float  g_invdeg[NN];
__device__ int    g_csr[NE];
__device__ int    g_blksum[64];
__device__ uint4  g_xh[(size_t)NN * 16];   // x fp16 (128 cols)
__device__ uint4  g_hh[(size_t)NN * 32];   // hidden activations fp16
__device__ uint4  g_mh[(size_t)NN * 32];   // aggregated mean fp16
__device__ float4 g_pre[(size_t)NN * 64];  // pre-BN output: fp32 (layer2) or fp16 (layers 0/1)
__device__ __half g_wh[262144];            // all 6 weights fp16, [D][K]
__device__ float  g_sum[768];              // 3 layers x 256
__device__ float  g_sumsq[768];

#define OFF_WN0 0
#define OFF_WS0 32768
#define OFF_WN1 65536
#define OFF_WS1 131072
#define OFF_WN2 196608
#define OFF_WS2 229376

#define AST 20   // unsigned units per smem row (80B): 16B-aligned rows, ldmatrix conflict-free

// ---------------- helpers ----------------
__device__ __forceinline__ void mma_fp16(float* c, const unsigned* a, const unsigned* b) {
    asm("mma.sync.aligned.m16n8k16.row.col.f32.f16.f16.f32 "
        "{%0,%1,%2,%3}, {%4,%5,%6,%7}, {%8,%9}, {%0,%1,%2,%3};"
        : "+f"(c[0]), "+f"(c[1]), "+f"(c[2]), "+f"(c[3])
        : "r"(a[0]), "r"(a[1]), "r"(a[2]), "r"(a[3]),
          "r"(b[0]), "r"(b[1]));
}
__device__ __forceinline__ void ldsm_x4(unsigned* r, uint32_t addr) {
    asm volatile("ldmatrix.sync.aligned.m8n8.x4.shared.b16 {%0,%1,%2,%3}, [%4];"
        : "=r"(r[0]), "=r"(r[1]), "=r"(r[2]), "=r"(r[3]) : "r"(addr));
}
__device__ __forceinline__ void cp_async16(uint32_t dst, const void* src, int src_size) {
    asm volatile("cp.async.cg.shared.global [%0], [%1], 16, %2;"
        :: "r"(dst), "l"(src), "r"(src_size));
}
__device__ __forceinline__ void cp_commit() {
    asm volatile("cp.async.commit_group;");
}
__device__ __forceinline__ void cp_wait0() {
    asm volatile("cp.async.wait_group 0;");
}

// ---------------- CSR build ----------------
__global__ void k_zero_cnt() {
    int i = blockIdx.x * blockDim.x + threadIdx.x;
    if (i < NN) { g_cnt[i] = 0; g_fill[i] = 0; }
    if (i < 768) { g_sum[i] = 0.f; g_sumsq[i] = 0.f; }
}

__global__ void k_hist(const int* __restrict__ dst) {
    int e = blockIdx.x * blockDim.x + threadIdx.x;
    if (e < NE) atomicAdd(&g_cnt[dst[e]], 1);
}

__global__ void k_scan1() {
    __shared__ int wsum[32];
    const int tid  = threadIdx.x;
    const int lane = tid & 31;
    const int wid  = tid >> 5;
    const int i = blockIdx.x * 1024 + tid;
    int v = (i < NN) ? g_cnt[i] : 0;
    int x = v;
    #pragma unroll
    for (int d = 1; d < 32; d <<= 1) {
        int t = __shfl_up_sync(0xffffffffu, x, d);
        if (lane >= d) x += t;
    }
    if (lane == 31) wsum[wid] = x;
    __syncthreads();
    if (wid == 0) {
        int w = wsum[lane];
        #pragma unroll
        for (int d = 1; d < 32; d <<= 1) {
            int t = __shfl_up_sync(0xffffffffu, w, d);
            if (lane >= d) w += t;
        }
        wsum[lane] = w;
    }
    __syncthreads();
    int incl = x + (wid ? wsum[wid - 1] : 0);
    if (i < NN) {
        g_rowptr[i + 1] = incl;
        g_invdeg[i] = 1.0f / (float)max(v, 1);
    }
    if (tid == 1023) g_blksum[blockIdx.x] = incl;
}

__global__ void k_scan23() {
    __shared__ int sv[64];
    const int tid = threadIdx.x;
    const int bid = blockIdx.x;
    if (tid < 64) sv[tid] = (tid < bid) ? g_blksum[tid] : 0;
    __syncthreads();
    if (tid < 32) {
        int v = sv[tid] + sv[tid + 32];
        #pragma unroll
        for (int d = 16; d; d >>= 1) v += __shfl_down_sync(0xffffffffu, v, d);
        if (tid == 0) sv[0] = v;
    }
    __syncthreads();
    const int off = sv[0];
    const int i = bid * 1024 + tid;
    if (i < NN) g_rowptr[i + 1] += off;
    if (i == 0) g_rowptr[0] = 0;
}

__global__ void k_fill(const int* __restrict__ src, const int* __restrict__ dst) {
    int e = blockIdx.x * blockDim.x + threadIdx.x;
    if (e < NE) {
        int d = dst[e];
        int p = g_rowptr[d] + atomicAdd(&g_fill[d], 1);
        g_csr[p] = src[e];
    }
}

// ---------------- x -> fp16 convert ----------------
__global__ void k_cvtx(const float* __restrict__ x) {
    const int total = NN * 16;
    int i = blockIdx.x * blockDim.x + threadIdx.x;
    if (i >= total) return;
    const float4* xp = reinterpret_cast<const float4*>(x);
    float4 a = xp[i * 2], b = xp[i * 2 + 1];
    uint4 o;
    __half2* op = (__half2*)&o;
    op[0] = __floats2half2_rn(a.x, a.y);
    op[1] = __floats2half2_rn(a.z, a.w);
    op[2] = __floats2half2_rn(b.x, b.y);
    op[3] = __floats2half2_rn(b.z, b.w);
    g_xh[i] = o;
}

// ---------------- all 6 weight transposes in one launch ----------------
__global__ void k_cvtw_all(const float* __restrict__ w0, const float* __restrict__ w1,
                           const float* __restrict__ w2, const float* __restrict__ w3,
                           const float* __restrict__ w4, const float* __restrict__ w5) {
    __shared__ float t[32][33];
    const int wi = blockIdx.z;
    const float* w; int K, D, off;
    switch (wi) {
        case 0:  w = w0; K = 128; D = 256; off = OFF_WN0; break;
        case 1:  w = w1; K = 128; D = 256; off = OFF_WS0; break;
        case 2:  w = w2; K = 256; D = 256; off = OFF_WN1; break;
        case 3:  w = w3; K = 256; D = 256; off = OFF_WS1; break;
        case 4:  w = w4; K = 256; D = 128; off = OFF_WN2; break;
        default: w = w5; K = 256; D = 128; off = OFF_WS2; break;
    }
    const int d0 = blockIdx.x * 32, k0 = blockIdx.y * 32;
    if (d0 >= D || k0 >= K) return;
    const int tx = threadIdx.x, ty = threadIdx.y;
    #pragma unroll
    for (int i = ty; i < 32; i += 8)
        t[i][tx] = w[(size_t)(k0 + i) * D + d0 + tx];
    __syncthreads();
    #pragma unroll
    for (int i = ty; i < 32; i += 8)
        g_wh[off + (size_t)(d0 + i) * K + k0 + tx] = __float2half_rn(t[tx][i]);
}

// ---------------- mean aggregation (R15 form) ----------------
template<int DIN, bool FROMX>
__global__ void k_agg() {
    const int TPN = DIN / 8;
    int t = blockIdx.x * blockDim.x + threadIdx.x;
    int node = t / TPN;
    if (node >= NN) return;
    int c8 = t % TPN;
    const uint4* __restrict__ hin = FROMX ? g_xh : g_hh;
    int beg = g_rowptr[node], end = g_rowptr[node + 1];
    float a0 = 0.f, a1 = 0.f, a2 = 0.f, a3 = 0.f;
    float a4 = 0.f, a5 = 0.f, a6 = 0.f, a7 = 0.f;
    for (int e = beg; e < end; e++) {
        int s = g_csr[e];
        uint4 u = hin[(size_t)s * TPN + c8];
        const __half2* hp = (const __half2*)&u;
        float2 f0 = __half22float2(hp[0]);
        float2 f1 = __half22float2(hp[1]);
        float2 f2 = __half22float2(hp[2]);
        float2 f3 = __half22float2(hp[3]);
        a0 += f0.x; a1 += f0.y; a2 += f1.x; a3 += f1.y;
        a4 += f2.x; a5 += f2.y; a6 += f3.x; a7 += f3.y;
    }
    float inv = g_invdeg[node];
    uint4 o;
    __half2* op = (__half2*)&o;
    op[0] = __floats2half2_rn(a0 * inv, a1 * inv);
    op[1] = __floats2half2_rn(a2 * inv, a3 * inv);
    op[2] = __floats2half2_rn(a4 * inv, a5 * inv);
    op[3] = __floats2half2_rn(a6 * inv, a7 * inv);
    g_mh[(size_t)node * TPN + c8] = o;
}

// ---------------- fused dual GEMM: 128x64 tile, 32-wide K chunks, cp.async x2,
//                  A-x4 + B-x4-packed ldmatrix ----------------
// HALFPRE: store pre-activations as fp16 (layers 0/1); else fp32 (layer 2).
template<int K, int DOUT, bool FROMX, bool HALFPRE>
__global__ __launch_bounds__(256) void k_gemm(
    int off1, int off2, const float* __restrict__ bias, int layer)
{
    __shared__ unsigned As2[2][128 * AST];
    __shared__ unsigned Bs2[2][64 * AST];

    const int tid    = threadIdx.x;
    const int lane   = tid & 31;
    const int wid    = tid >> 5;
    const int mbase  = (wid >> 1) * 32;
    const int nbase  = (wid & 1) * 32;
    const int n0 = blockIdx.x * 64;
    const int m0 = blockIdx.y * 128;

    const int a_row = tid >> 1;         // 0..127
    const int a_g   = tid & 1;          // stages 16B groups {a_g, a_g+2} of 4
    const int b_n   = tid >> 2;         // 0..63
    const int b_g   = tid & 3;          // one 16B group of 4

    const int THK = K / 8;
    const int CPP = K / 32;             // 32-wide chunks per phase
    const int NCH = 2 * CPP;
    const uint4* A1 = g_mh;
    const uint4* A2 = FROMX ? g_xh : g_hh;
    const __half* B1w = g_wh + off1;
    const __half* B2w = g_wh + off2;

    const uint32_t sbA = (uint32_t)__cvta_generic_to_shared(&As2[0][0]);
    const uint32_t sbB = (uint32_t)__cvta_generic_to_shared(&Bs2[0][0]);
    const uint32_t ABYTES = 128u * AST * 4u;
    const uint32_t BBYTES = 64u * AST * 4u;

    const uint32_t dstA0 = sbA + 4u * (a_row * AST + a_g * 4);
    const uint32_t dstA1 = dstA0 + 32u;        // group a_g+2
    const uint32_t dstB  = sbB + 4u * (b_n * AST + b_g * 4);

    const int gr   = m0 + a_row;
    const int grc  = (gr < NN) ? gr : 0;
    const int asz  = (gr < NN) ? 16 : 0;

    // ldmatrix addresses (buffer 0, k16-half 0)
    const int quad = lane >> 3, lr = lane & 7;
    uint32_t addrA[2];
    #pragma unroll
    for (int sm = 0; sm < 2; sm++) {
        int row = mbase + sm * 16 + (quad & 1) * 8 + lr;
        int kp  = (quad >> 1) * 4;
        addrA[sm] = sbA + 4u * (row * AST + kp);
    }
    // B x4: pair p covers sn=2p,2p+1. mat q = lane>>3: snOff=q>>1, kh=q&1
    uint32_t addrB4[2];
    #pragma unroll
    for (int p = 0; p < 2; p++) {
        int snOff = quad >> 1;          // 0 or 1 within the pair
        int kh    = quad & 1;           // k-sub-half (kp 0 or 4)
        int row = nbase + (2 * p + snOff) * 8 + lr;
        addrB4[p] = sbB + 4u * (row * AST + kh * 4);
    }

    float acc[2][4][4];
    #pragma unroll
    for (int i = 0; i < 2; i++)
        #pragma unroll
        for (int j = 0; j < 4; j++)
            #pragma unroll
            for (int r = 0; r < 4; r++) acc[i][j][r] = 0.f;

    auto stage = [&](int c, int b) {
        const int phase = (c >= CPP);
        const int k0    = (c - phase * CPP) * 32;
        const uint4*  A = phase ? A2 : A1;
        const __half* B = phase ? B2w : B1w;
        const uint4* as = A + (size_t)grc * THK + (k0 >> 3);
        cp_async16(dstA0 + b * ABYTES, as + a_g,     asz);
        cp_async16(dstA1 + b * ABYTES, as + a_g + 2, asz);
        cp_async16(dstB  + b * BBYTES,
                   B + (size_t)(n0 + b_n) * K + k0 + b_g * 8, 16);
        cp_commit();
    };

    stage(0, 0);
    cp_wait0();
    __syncthreads();

    for (int c = 0; c < NCH; c++) {
        const int buf = c & 1;
        if (c + 1 < NCH) stage(c + 1, buf ^ 1);

        const uint32_t oA = buf * ABYTES;
        const uint32_t oB = buf * BBYTES;
        #pragma unroll
        for (int h = 0; h < 2; h++) {
            const uint32_t hk = h * 32u;   // +8 unsigned = second k16 half
            unsigned af[2][4];
            ldsm_x4(af[0], addrA[0] + oA + hk);
            ldsm_x4(af[1], addrA[1] + oA + hk);
            #pragma unroll
            for (int p = 0; p < 2; p++) {
                unsigned bq[4];            // {snA kh0, snA kh1, snB kh0, snB kh1}
                ldsm_x4(bq, addrB4[p] + oB + hk);
                mma_fp16(acc[0][2 * p],     af[0], bq);
                mma_fp16(acc[0][2 * p + 1], af[0], bq + 2);
                mma_fp16(acc[1][2 * p],     af[1], bq);
                mma_fp16(acc[1][2 * p + 1], af[1], bq + 2);
            }
        }

        if (c + 1 < NCH) {
            cp_wait0();
            __syncthreads();
        }
    }

    // ---------------- epilogue: bias + store + BN partials ----------------
    float*  Cf = (float*)g_pre;
    __half* Ch = (__half*)g_pre;

    #pragma unroll
    for (int sn = 0; sn < 4; sn++) {
        const int colg = n0 + nbase + sn * 8 + 2 * (lane & 3);
        const float bb0 = bias[colg];
        const float bb1 = bias[colg + 1];
        float s0 = 0.f, s1 = 0.f, q0 = 0.f, q1 = 0.f;
        #pragma unroll
        for (int sm = 0; sm < 2; sm++) {
            const int r0 = m0 + mbase + sm * 16 + (lane >> 2);
            const int r1 = r0 + 8;
            float v0 = acc[sm][sn][0] + bb0;
            float v1 = acc[sm][sn][1] + bb1;
            float v2 = acc[sm][sn][2] + bb0;
            float v3 = acc[sm][sn][3] + bb1;
            if (r0 < NN) {
                if (HALFPRE)
                    *reinterpret_cast<__half2*>(Ch + (size_t)r0 * DOUT + colg) =
                        __floats2half2_rn(v0, v1);
                else
                    *reinterpret_cast<float2*>(Cf + (size_t)r0 * DOUT + colg) =
                        make_float2(v0, v1);
                s0 += v0; q0 += v0 * v0;
                s1 += v1; q1 += v1 * v1;
            }
            if (r1 < NN) {
                if (HALFPRE)
                    *reinterpret_cast<__half2*>(Ch + (size_t)r1 * DOUT + colg) =
                        __floats2half2_rn(v2, v3);
                else
                    *reinterpret_cast<float2*>(Cf + (size_t)r1 * DOUT + colg) =
                        make_float2(v2, v3);
                s0 += v2; q0 += v2 * v2;
                s1 += v3; q1 += v3 * v3;
            }
        }
        #pragma unroll
        for (int d = 16; d >= 4; d >>= 1) {
            s0 += __shfl_down_sync(0xffffffffu, s0, d);
            s1 += __shfl_down_sync(0xffffffffu, s1, d);
            q0 += __shfl_down_sync(0xffffffffu, q0, d);
            q1 += __shfl_down_sync(0xffffffffu, q1, d);
        }
        if (lane < 4) {
            const int cg = n0 + nbase + sn * 8 + 2 * lane;
            atomicAdd(&g_sum  [layer * 256 + cg],     s0);
            atomicAdd(&g_sum  [layer * 256 + cg + 1], s1);
            atomicAdd(&g_sumsq[layer * 256 + cg],     q0);
            atomicAdd(&g_sumsq[layer * 256 + cg + 1], q1);
        }
    }
}

// ---------------- BN finalize (in-block) + apply ----------------
// HALFIN: pre stored as fp16 (layers 0/1); else fp32 (layer 2).
template<int DOUT, bool RELU, bool TOOUT, bool HALFIN>
__global__ __launch_bounds__(256) void k_bnapply(
    const float* __restrict__ gamma, const float* __restrict__ beta,
    int layer, float* __restrict__ outp)
{
    __shared__ float s_scale[DOUT], s_shift[DOUT];
    const int tid = threadIdx.x;
    if (tid < DOUT) {
        float mu  = g_sum[layer * 256 + tid] * (1.0f / NN);
        float var = g_sumsq[layer * 256 + tid] * (1.0f / NN) - mu * mu;
        float sc  = gamma[tid] * rsqrtf(var + 1e-5f);
        s_scale[tid] = sc;
        s_shift[tid] = beta[tid] - mu * sc;
    }
    __syncthreads();

    const int total = NN * (DOUT / 8);
    int i = blockIdx.x * blockDim.x + tid;
    if (i >= total) return;
    int c8 = (i % (DOUT / 8)) * 8;
    float p[8];
    if (HALFIN) {
        uint4 u = reinterpret_cast<const uint4*>(g_pre)[i];
        const __half2* hp = (const __half2*)&u;
        float2 f0 = __half22float2(hp[0]);
        float2 f1 = __half22float2(hp[1]);
        float2 f2 = __half22float2(hp[2]);
        float2 f3 = __half22float2(hp[3]);
        p[0] = f0.x; p[1] = f0.y; p[2] = f1.x; p[3] = f1.y;
        p[4] = f2.x; p[5] = f2.y; p[6] = f3.x; p[7] = f3.y;
    } else {
        float4 v0 = g_pre[i * 2];
        float4 v1 = g_pre[i * 2 + 1];
        p[0] = v0.x; p[1] = v0.y; p[2] = v0.z; p[3] = v0.w;
        p[4] = v1.x; p[5] = v1.y; p[6] = v1.z; p[7] = v1.w;
    }
    float r[8];
    #pragma unroll
    for (int j = 0; j < 8; j++) {
        r[j] = p[j] * s_scale[c8 + j] + s_shift[c8 + j];
        if (RELU) r[j] = fmaxf(r[j], 0.f);
    }
    if (TOOUT) {
        float4* op = reinterpret_cast<float4*>(outp);
        op[i * 2]     = make_float4(r[0], r[1], r[2], r[3]);
        op[i * 2 + 1] = make_float4(r[4], r[5], r[6], r[7]);
    } else {
        uint4 o;
        __half2* hp = (__half2*)&o;
        hp[0] = __floats2half2_rn(r[0], r[1]);
        hp[1] = __floats2half2_rn(r[2], r[3]);
        hp[2] = __floats2half2_rn(r[4], r[5]);
        hp[3] = __floats2half2_rn(r[6], r[7]);
        g_hh[i] = o;
    }
}

// ---------------- launch ----------------
extern "C" void kernel_launch(void* const* d_in, const int* in_sizes, int n_in,
                              void* d_out, int out_size) {
    const float* x    = (const float*)d_in[0];
    const int*   ei   = (const int*)d_in[1];
    const int*   esrc = ei;
    const int*   edst = ei + NE;
    const float* wn0 = (const float*)d_in[2];
    const float* ws0 = (const float*)d_in[3];
    const float* b0  = (const float*)d_in[4];
    const float* g0  = (const float*)d_in[5];
    const float* be0 = (const float*)d_in[6];
    const float* wn1 = (const float*)d_in[7];
    const float* ws1 = (const float*)d_in[8];
    const float* b1  = (const float*)d_in[9];
    const float* g1  = (const float*)d_in[10];
    const float* be1 = (const float*)d_in[11];
    const float* wn2 = (const float*)d_in[12];
    const float* ws2 = (const float*)d_in[13];
    const float* b2  = (const float*)d_in[14];
    const float* g2  = (const float*)d_in[15];
    const float* be2 = (const float*)d_in[16];
    float* out = (float*)d_out;

    const int NBLK = (NN + 1023) / 1024;   // 49

    k_zero_cnt<<<(NN + 255) / 256, 256>>>();
    k_hist<<<(NE + 255) / 256, 256>>>(edst);
    k_scan1<<<NBLK, 1024>>>();
    k_scan23<<<NBLK, 1024>>>();
    k_fill<<<(NE + 255) / 256, 256>>>(esrc, edst);
    k_cvtx<<<(NN * 16 + 255) / 256, 256>>>(x);
    k_cvtw_all<<<dim3(8, 8, 6), dim3(32, 8)>>>(wn0, ws0, wn1, ws1, wn2, ws2);

    const int M_TILES = (NN + 127) / 128;

    // ---- layer 0: 128 -> 256 (fp16 pre) ----
    k_agg<128, true><<<(NN * 16 + 255) / 256, 256>>>();
    k_gemm<128, 256, true, true><<<dim3(4, M_TILES), 256>>>(OFF_WN0, OFF_WS0, b0, 0);
    k_bnapply<256, true, false, true><<<(NN * 32 + 255) / 256, 256>>>(g0, be0, 0, nullptr);

    // ---- layer 1: 256 -> 256 (fp16 pre) ----
    k_agg<256, false><<<(NN * 32 + 255) / 256, 256>>>();
    k_gemm<256, 256, false, true><<<dim3(4, M_TILES), 256>>>(OFF_WN1, OFF_WS1, b1, 1);
    k_bnapply<256, true, false, true><<<(NN * 32 + 255) / 256, 256>>>(g1, be1, 1, nullptr);

    // ---- layer 2: 256 -> 128 (fp32 pre, fp32 out) ----
    k_agg<256, false><<<(NN * 32 + 255) / 256, 256>>>();
    k_gemm<256, 128, false, false><<<dim3(2, M_TILES), 256>>>(OFF_WN2, OFF_WS2, b2, 2);
    k_bnapply<128, false, true, false><<<(NN * 16 + 255) / 256, 256>>>(g2, be2, 2, out);
}